// round 2
// baseline (speedup 1.0000x reference)
#include <cuda_runtime.h>
#include <math.h>
#include <stdint.h>

// Problem constants
#define TT   12
#define NN   4096
#define FIN  64
#define HG   128
#define HL   128
#define CC   10
#define EE   65536
#define G4   512   // 4*HL

typedef unsigned long long ull;

// ---------------- scratch (static device arrays; no cudaMalloc) ----------------
__device__ float g_hw[(size_t)NN * HG];
__device__ float g_h [(size_t)NN * HG];
__device__ float g_X1[(size_t)NN * G4];
__device__ float g_X2[(size_t)NN * G4];
__device__ float g_h1all[(size_t)NN * HL];
__device__ float g_h2all[(size_t)NN * HL];
__device__ float g_deg[NN];
__device__ float g_dinv[NN];
__device__ int   g_cnt[NN];
__device__ int   g_off[NN + 1];
__device__ int   g_pos[NN];
__device__ int   g_esrc[EE];
__device__ float g_enorm[EE];
__device__ float g_Wih1T[HL * G4], g_Wih2T[HL * G4];

// ---------------- graph preprocessing ----------------
__global__ void k_init() {
    int i = blockIdx.x * blockDim.x + threadIdx.x;
    if (i < NN) { g_deg[i] = 1.0f; g_cnt[i] = 0; }   // self-loop weight folded in
}

__global__ void k_edge(const int* __restrict__ ei, const float* __restrict__ ew) {
    int e = blockIdx.x * blockDim.x + threadIdx.x;
    if (e < EE) {
        int d = ei[EE + e];
        atomicAdd(&g_deg[d], ew[e]);
        atomicAdd(&g_cnt[d], 1);
    }
}

__global__ void k_dinv() {
    int i = blockIdx.x * blockDim.x + threadIdx.x;
    if (i < NN) {
        float d = g_deg[i];
        g_dinv[i] = d > 0.0f ? rsqrtf(d) : 0.0f;
    }
}

// exclusive prefix sum over g_cnt[4096]  (1 block, 1024 threads x 4)
__global__ void k_scan() {
    __shared__ int s[1024];
    int tid = threadIdx.x;
    int base = tid * 4;
    int v[4];
    int tot = 0;
#pragma unroll
    for (int i = 0; i < 4; i++) { v[i] = g_cnt[base + i]; tot += v[i]; }
    s[tid] = tot;
    __syncthreads();
    for (int d = 1; d < 1024; d <<= 1) {
        int t = (tid >= d) ? s[tid - d] : 0;
        __syncthreads();
        s[tid] += t;
        __syncthreads();
    }
    int excl = (tid == 0) ? 0 : s[tid - 1];
#pragma unroll
    for (int i = 0; i < 4; i++) {
        g_off[base + i] = excl;
        g_pos[base + i] = excl;
        excl += v[i];
    }
    if (tid == 1023) g_off[NN] = s[1023];
}

__global__ void k_fill(const int* __restrict__ ei, const float* __restrict__ ew) {
    int e = blockIdx.x * blockDim.x + threadIdx.x;
    if (e < EE) {
        int s = ei[e];
        int d = ei[EE + e];
        int p = atomicAdd(&g_pos[d], 1);
        g_esrc[p] = s;
        g_enorm[p] = g_dinv[s] * ew[e] * g_dinv[d];
    }
}

// ---------------- weight transpose:  W[OC][K] -> Wt[K][OC] ----------------
__global__ void k_tr(const float* __restrict__ W, float* __restrict__ Wt, int OC, int K) {
    int i = blockIdx.x * blockDim.x + threadIdx.x;
    if (i < OC * K) {
        int o = i / K, k = i % K;
        Wt[k * OC + o] = W[i];
    }
}

// ---------------- GEMM:  C[M][OC] = A[M][K] @ Wt   (Wt stored [K][OC]) ----------------
template <int K, int OC, int ROWS, bool BIAS2>
__global__ void k_gemm_kn(const float* __restrict__ A, const float* __restrict__ Wt,
                          const float* __restrict__ ba, const float* __restrict__ bb,
                          float* __restrict__ Cc) {
    __shared__ float As[ROWS][K];
    const int c = threadIdx.x;                 // output column, blockDim = OC
    const size_t row0 = (size_t)blockIdx.x * ROWS;
    for (int idx = c; idx < ROWS * K; idx += OC)
        As[idx / K][idx % K] = A[row0 * K + idx];
    __syncthreads();

    float binit = 0.0f;
    if constexpr (BIAS2) binit = ba[c] + bb[c];
    float acc[ROWS];
#pragma unroll
    for (int r = 0; r < ROWS; r++) acc[r] = binit;

#pragma unroll 4
    for (int k4 = 0; k4 < K / 4; k4++) {
        int k = k4 * 4;
        float w0 = Wt[(size_t)(k + 0) * OC + c];
        float w1 = Wt[(size_t)(k + 1) * OC + c];
        float w2 = Wt[(size_t)(k + 2) * OC + c];
        float w3 = Wt[(size_t)(k + 3) * OC + c];
#pragma unroll
        for (int r = 0; r < ROWS; r++) {
            float4 a = ((const float4*)As[r])[k4];
            acc[r] += a.x * w0 + a.y * w1 + a.z * w2 + a.w * w3;
        }
    }
#pragma unroll
    for (int r = 0; r < ROWS; r++)
        Cc[(row0 + r) * OC + c] = acc[r];
}

// ---------------- GCN aggregation (CSR gather) + bias + exact GELU ----------------
__global__ void k_gather(const float* __restrict__ hw, const float* __restrict__ b,
                         float* __restrict__ out) {
    const int n = blockIdx.x;
    const int h = threadIdx.x;                 // 0..127
    float di = g_dinv[n];
    float acc = hw[n * HG + h] * di * di;      // self loop (weight 1)
    int e0 = g_off[n], e1 = g_off[n + 1];
    for (int e = e0; e < e1; e++)
        acc += hw[g_esrc[e] * HG + h] * g_enorm[e];
    float x = acc + b[h];
    out[(size_t)n * HG + h] = 0.5f * x * (1.0f + erff(x * 0.70710678118654752f));
}

// ---------------- fast activations ----------------
__device__ __forceinline__ float sigm_f(float x) {
    return __fdividef(1.0f, 1.0f + __expf(-x));
}
__device__ __forceinline__ float tanh_f(float x) {
    return 1.0f - __fdividef(2.0f, 1.0f + __expf(2.0f * x));
}

// ---------------- LSTM scan over 4096 nodes, batch=1 ----------------
// One persistent block, 512 threads. Thread t owns gate row r = (t&3)*128 + (t>>2).
// Weights: k=0..95 in registers (48 f32x2 pairs), k=96..127 in dynamic smem.
// X[n][r] = precomputed Wih@x_n + bih + bhh.  Dot products use packed fma.rn.f32x2.
__global__ __launch_bounds__(512, 1) void k_lstm_scan(
    const float* __restrict__ X,      // [NN][G4]
    const float* __restrict__ Whh,    // [G4][HL] row-major
    float* __restrict__ hall)         // [NN][HL]
{
    extern __shared__ ull dyn[];
    float* sh = (float*)dyn;                   // sh[2][HL] = 256 floats
    ull*   sW = dyn + 128;                     // sW[i*512 + t], i=0..15  (64KB)

    const int t = threadIdx.x;
    const int g = t & 3;
    const int u = t >> 2;
    const int r = g * HL + u;

    ull w[48];
    {
        const ull* wrow = (const ull*)(Whh + (size_t)r * HL);
#pragma unroll
        for (int i = 0; i < 48; i++) w[i] = wrow[i];
#pragma unroll
        for (int i = 0; i < 16; i++) sW[i * 512 + t] = wrow[48 + i];
    }
    if (t < HL) sh[t] = 0.0f;                  // buffer 0
    float c = 0.0f;
    float xv = X[r];
    __syncthreads();

    const int lanebase = (t & 31) & ~3;

    for (int n = 0; n < NN; n++) {
        const ull* hb = (const ull*)(sh + (n & 1) * HL);
        float xnext = (n + 1 < NN) ? X[(size_t)(n + 1) * G4 + r] : 0.0f;

        ull acc = 0ull;                        // packed (0.0f, 0.0f)
#pragma unroll
        for (int i = 0; i < 48; i++)
            asm("fma.rn.f32x2 %0, %1, %2, %0;" : "+l"(acc) : "l"(w[i]), "l"(hb[i]));
#pragma unroll
        for (int i = 0; i < 16; i++)
            asm("fma.rn.f32x2 %0, %1, %2, %0;" : "+l"(acc) : "l"(sW[i * 512 + t]), "l"(hb[48 + i]));

        float a_lo, a_hi;
        asm("mov.b64 {%0, %1}, %2;" : "=f"(a_lo), "=f"(a_hi) : "l"(acc));
        float s = a_lo + a_hi + xv;

        float gate = (g == 2) ? tanh_f(s) : sigm_f(s);

        float i_ = __shfl_sync(0xffffffffu, gate, lanebase + 0);
        float f_ = __shfl_sync(0xffffffffu, gate, lanebase + 1);
        float gg = __shfl_sync(0xffffffffu, gate, lanebase + 2);
        float o_ = __shfl_sync(0xffffffffu, gate, lanebase + 3);

        c = f_ * c + i_ * gg;
        float hn = o_ * tanh_f(c);

        if (g == 0) {
            sh[((n + 1) & 1) * HL + u] = hn;
            hall[(size_t)n * HL + u] = hn;
        }
        xv = xnext;
        __syncthreads();
    }
}

// ---------------- final FC: out[n][c] = h2all[n] . Wfc[c] + bfc[c] ----------------
__global__ void k_fc(const float* __restrict__ h2all, const float* __restrict__ Wfc,
                     const float* __restrict__ bfc, float* __restrict__ out) {
    const int n = blockIdx.x;
    const int lane = threadIdx.x;              // 32 threads
    float4 hv = ((const float4*)(h2all + (size_t)n * HL))[lane];
#pragma unroll
    for (int c = 0; c < CC; c++) {
        float4 w = ((const float4*)(Wfc + (size_t)c * HL))[lane];
        float p = hv.x * w.x + hv.y * w.y + hv.z * w.z + hv.w * w.w;
#pragma unroll
        for (int s = 16; s; s >>= 1) p += __shfl_xor_sync(0xffffffffu, p, s);
        if (lane == 0) out[n * CC + c] = p + bfc[c];
    }
}

// ---------------- launch ----------------
extern "C" void kernel_launch(void* const* d_in, const int* in_sizes, int n_in,
                              void* d_out, int out_size) {
    const float* x    = (const float*)d_in[0];
    const int*   ei   = (const int*)  d_in[1];
    const float* ew   = (const float*)d_in[2];
    const float* W1   = (const float*)d_in[3];
    const float* b1   = (const float*)d_in[4];
    const float* W2   = (const float*)d_in[5];
    const float* b2   = (const float*)d_in[6];
    const float* W3   = (const float*)d_in[7];
    const float* b3   = (const float*)d_in[8];
    const float* Wih1 = (const float*)d_in[9];
    const float* Whh1 = (const float*)d_in[10];
    const float* bih1 = (const float*)d_in[11];
    const float* bhh1 = (const float*)d_in[12];
    const float* Wih2 = (const float*)d_in[13];
    const float* Whh2 = (const float*)d_in[14];
    const float* bih2 = (const float*)d_in[15];
    const float* bhh2 = (const float*)d_in[16];
    const float* Wfc  = (const float*)d_in[17];
    const float* bfc  = (const float*)d_in[18];
    float* out = (float*)d_out;

    float *d_hw, *d_h, *d_X1, *d_X2, *d_h1all, *d_h2all, *d_Wih1T, *d_Wih2T;
    cudaGetSymbolAddress((void**)&d_hw,    g_hw);
    cudaGetSymbolAddress((void**)&d_h,     g_h);
    cudaGetSymbolAddress((void**)&d_X1,    g_X1);
    cudaGetSymbolAddress((void**)&d_X2,    g_X2);
    cudaGetSymbolAddress((void**)&d_h1all, g_h1all);
    cudaGetSymbolAddress((void**)&d_h2all, g_h2all);
    cudaGetSymbolAddress((void**)&d_Wih1T, g_Wih1T);
    cudaGetSymbolAddress((void**)&d_Wih2T, g_Wih2T);

    static int smem_set = 0;
    const int SCAN_SMEM = 1024 + 16 * 512 * 8;   // sh[2][128] + sW (64KB) = 66560 B
    if (!smem_set) {
        cudaFuncSetAttribute(k_lstm_scan, cudaFuncAttributeMaxDynamicSharedMemorySize, SCAN_SMEM);
        smem_set = 1;
    }

    // graph preprocessing (CSR by destination) + degree norm
    k_init<<<NN / 256, 256>>>();
    k_edge<<<EE / 256, 256>>>(ei, ew);
    k_dinv<<<NN / 256, 256>>>();
    k_scan<<<1, 1024>>>();
    k_fill<<<EE / 256, 256>>>(ei, ew);

    // transpose Wih weights to [K][OC]
    int trB = (HL * G4 + 255) / 256;
    k_tr<<<trB, 256>>>(Wih1, d_Wih1T, G4, HL);
    k_tr<<<trB, 256>>>(Wih2, d_Wih2T, G4, HL);

    // GCN on t=11 slice only (only slice that affects the output)
    const float* x11 = x + (size_t)11 * NN * FIN;
    k_gemm_kn<64, 128, 16, false><<<NN / 16, 128>>>(x11, W1, nullptr, nullptr, d_hw);
    k_gather<<<NN, 128>>>(d_hw, b1, d_h);
    k_gemm_kn<128, 128, 16, false><<<NN / 16, 128>>>(d_h, W2, nullptr, nullptr, d_hw);
    k_gather<<<NN, 128>>>(d_hw, b2, d_h);
    k_gemm_kn<128, 128, 16, false><<<NN / 16, 128>>>(d_h, W3, nullptr, nullptr, d_hw);
    k_gather<<<NN, 128>>>(d_hw, b3, d_h);

    // X1 = h @ Wih1^T + (bih1 + bhh1)
    k_gemm_kn<128, 512, 16, true><<<NN / 16, 512>>>(d_h, d_Wih1T, bih1, bhh1, d_X1);

    // LSTM layer 1 scan over 4096 nodes
    k_lstm_scan<<<1, 512, SCAN_SMEM>>>(d_X1, Whh1, d_h1all);

    // X2 = h1 @ Wih2^T + (bih2 + bhh2)
    k_gemm_kn<128, 512, 16, true><<<NN / 16, 512>>>(d_h1all, d_Wih2T, bih2, bhh2, d_X2);

    // LSTM layer 2 scan
    k_lstm_scan<<<1, 512, SCAN_SMEM>>>(d_X2, Whh2, d_h2all);

    // final FC
    k_fc<<<NN, 32>>>(d_h2all, Wfc, bfc, out);
}

// round 4
// speedup vs baseline: 1.5938x; 1.5938x over previous
#include <cuda_runtime.h>
#include <math.h>
#include <stdint.h>

// Problem constants
#define TT   12
#define NN   4096
#define FIN  64
#define HG   128
#define HL   128
#define CC   10
#define EE   65536
#define G4   512   // 4*HL
#define CHUNK   64
#define NCHUNK  (NN / CHUNK)   // 64
#define NGB     8              // gemm blocks in fused kernel

typedef unsigned long long ull;

#define FMA2(acc, a, b) asm("fma.rn.f32x2 %0, %1, %2, %0;" : "+l"(acc) : "l"(a), "l"(b))
#define ADD2(d, a, b)   asm("add.rn.f32x2 %0, %1, %2;"     : "=l"(d)   : "l"(a), "l"(b))

// ---------------- scratch (static device arrays; no cudaMalloc) ----------------
__device__ float g_hw[(size_t)NN * HG];
__device__ float g_h [(size_t)NN * HG];
__device__ float g_X1[(size_t)NN * G4];
__device__ float g_X2[(size_t)NN * G4];
__device__ float g_h1all[(size_t)NN * HL];
__device__ float g_h2all[(size_t)NN * HL];
__device__ float g_deg[NN];
__device__ float g_dinv[NN];
__device__ int   g_cnt[NN];
__device__ int   g_off[NN + 1];
__device__ int   g_pos[NN];
__device__ int   g_esrc[EE];
__device__ float g_enorm[EE];
__device__ float g_Wih1T[HL * G4], g_Wih2T[HL * G4];
__device__ int   g_prog1;
__device__ int   g_x2ready[NCHUNK];

// ---------------- graph preprocessing ----------------
__global__ void k_init() {
    int i = blockIdx.x * blockDim.x + threadIdx.x;
    if (i < NN) { g_deg[i] = 1.0f; g_cnt[i] = 0; }
    if (i == 0) g_prog1 = 0;
    if (i < NCHUNK) g_x2ready[i] = 0;
}

__global__ void k_edge(const int* __restrict__ ei, const float* __restrict__ ew) {
    int e = blockIdx.x * blockDim.x + threadIdx.x;
    if (e < EE) {
        int d = ei[EE + e];
        atomicAdd(&g_deg[d], ew[e]);
        atomicAdd(&g_cnt[d], 1);
    }
}

__global__ void k_dinv() {
    int i = blockIdx.x * blockDim.x + threadIdx.x;
    if (i < NN) {
        float d = g_deg[i];
        g_dinv[i] = d > 0.0f ? rsqrtf(d) : 0.0f;
    }
}

__global__ void k_scan() {
    __shared__ int s[1024];
    int tid = threadIdx.x;
    int base = tid * 4;
    int v[4];
    int tot = 0;
#pragma unroll
    for (int i = 0; i < 4; i++) { v[i] = g_cnt[base + i]; tot += v[i]; }
    s[tid] = tot;
    __syncthreads();
    for (int d = 1; d < 1024; d <<= 1) {
        int t = (tid >= d) ? s[tid - d] : 0;
        __syncthreads();
        s[tid] += t;
        __syncthreads();
    }
    int excl = (tid == 0) ? 0 : s[tid - 1];
#pragma unroll
    for (int i = 0; i < 4; i++) {
        g_off[base + i] = excl;
        g_pos[base + i] = excl;
        excl += v[i];
    }
    if (tid == 1023) g_off[NN] = s[1023];
}

__global__ void k_fill(const int* __restrict__ ei, const float* __restrict__ ew) {
    int e = blockIdx.x * blockDim.x + threadIdx.x;
    if (e < EE) {
        int s = ei[e];
        int d = ei[EE + e];
        int p = atomicAdd(&g_pos[d], 1);
        g_esrc[p] = s;
        g_enorm[p] = g_dinv[s] * ew[e] * g_dinv[d];
    }
}

// ---------------- weight transpose:  W[OC][K] -> Wt[K][OC] ----------------
__global__ void k_tr(const float* __restrict__ W, float* __restrict__ Wt, int OC, int K) {
    int i = blockIdx.x * blockDim.x + threadIdx.x;
    if (i < OC * K) {
        int o = i / K, k = i % K;
        Wt[k * OC + o] = W[i];
    }
}

// ---------------- GEMM:  C[M][OC] = A[M][K] @ Wt   (Wt stored [K][OC]) ----------------
template <int K, int OC, int ROWS, bool BIAS2>
__global__ void k_gemm_kn(const float* __restrict__ A, const float* __restrict__ Wt,
                          const float* __restrict__ ba, const float* __restrict__ bb,
                          float* __restrict__ Cc) {
    __shared__ float As[ROWS][K];
    const int c = threadIdx.x;
    const size_t row0 = (size_t)blockIdx.x * ROWS;
    for (int idx = c; idx < ROWS * K; idx += OC)
        As[idx / K][idx % K] = A[row0 * K + idx];
    __syncthreads();

    float binit = 0.0f;
    if constexpr (BIAS2) binit = ba[c] + bb[c];
    float acc[ROWS];
#pragma unroll
    for (int r = 0; r < ROWS; r++) acc[r] = binit;

#pragma unroll 4
    for (int k4 = 0; k4 < K / 4; k4++) {
        int k = k4 * 4;
        float w0 = Wt[(size_t)(k + 0) * OC + c];
        float w1 = Wt[(size_t)(k + 1) * OC + c];
        float w2 = Wt[(size_t)(k + 2) * OC + c];
        float w3 = Wt[(size_t)(k + 3) * OC + c];
#pragma unroll
        for (int r = 0; r < ROWS; r++) {
            float4 a = ((const float4*)As[r])[k4];
            acc[r] += a.x * w0 + a.y * w1 + a.z * w2 + a.w * w3;
        }
    }
#pragma unroll
    for (int r = 0; r < ROWS; r++)
        Cc[(row0 + r) * OC + c] = acc[r];
}

// ---------------- GCN aggregation (CSR gather) + bias + exact GELU ----------------
__global__ void k_gather(const float* __restrict__ hw, const float* __restrict__ b,
                         float* __restrict__ out) {
    const int n = blockIdx.x;
    const int h = threadIdx.x;
    float di = g_dinv[n];
    float acc = hw[n * HG + h] * di * di;
    int e0 = g_off[n], e1 = g_off[n + 1];
    for (int e = e0; e < e1; e++)
        acc += hw[g_esrc[e] * HG + h] * g_enorm[e];
    float x = acc + b[h];
    out[(size_t)n * HG + h] = 0.5f * x * (1.0f + erff(x * 0.70710678118654752f));
}

// ---------------- fast activations ----------------
__device__ __forceinline__ float sigm_f(float x) {
    return __fdividef(1.0f, 1.0f + __expf(-x));
}
__device__ __forceinline__ float tanh_f(float x) {
    return 1.0f - __fdividef(2.0f, 1.0f + __expf(2.0f * x));
}

// ================= fused pipelined LSTM kernel =================
// role 0:      layer-1 scan (producer of h1all, publishes g_prog1 per chunk)
// role 1..NGB: streaming GEMM  X2 = h1all @ Wih2T + bias  (publishes g_x2ready[c])
// role NGB+1:  layer-2 scan (consumer of X2)
//
// Scan: 512 threads, thread t owns gate row r = (t&3)*128 + (t>>2).
// Whh row: k=0..87 in registers (44 ull), k=88..127 in smem (10 ulonglong2 / thread).
// Dot products: packed fma.rn.f32x2, 4 independent accumulators (dep chain 11).

template <int LAYER>
__device__ __forceinline__ void scan_body(const float* __restrict__ X,
                                          const float* __restrict__ Whh,
                                          float* __restrict__ hall) {
    extern __shared__ ull dyn[];
    float* sh = (float*)dyn;                         // sh[2][HL]  (1KB)
    ulonglong2* sW2 = (ulonglong2*)(dyn + 128);      // sW2[i*512 + t], i=0..9 (80KB)

    const int t = threadIdx.x;
    const int g = t & 3;
    const int u = t >> 2;
    const int r = g * HL + u;

    ull w[44];
    {
        const ull* wrow = (const ull*)(Whh + (size_t)r * HL);
#pragma unroll
        for (int i = 0; i < 44; i++) w[i] = wrow[i];
#pragma unroll
        for (int i = 0; i < 10; i++) {
            ulonglong2 v;
            v.x = wrow[44 + 2 * i];
            v.y = wrow[44 + 2 * i + 1];
            sW2[i * 512 + t] = v;
        }
    }
    if (t < HL) { sh[t] = 0.0f; sh[HL + t] = 0.0f; }
    float c = 0.0f;
    float xv = 0.0f;
    if (LAYER == 0) xv = X[r];
    __syncthreads();

    const int lanebase = (t & 31) & ~3;

    for (int n = 0; n < NN; n++) {
        if (LAYER == 1 && (n & (CHUNK - 1)) == 0) {
            if (t == 0) {
                while (((volatile int*)g_x2ready)[n >> 6] == 0) {}
                __threadfence();
            }
            __syncthreads();
            xv = __ldcg(&X[(size_t)n * G4 + r]);
        }

        const ulonglong2* hb2 = (const ulonglong2*)(sh + (n & 1) * HL);

        // prefetch next X (safe only within an already-flagged chunk for LAYER 1)
        float xnext = 0.0f;
        bool pf = (n + 1 < NN) && (LAYER == 0 || ((n + 1) & (CHUNK - 1)) != 0);
        if (pf) xnext = (LAYER == 1) ? __ldcg(&X[(size_t)(n + 1) * G4 + r])
                                     : X[(size_t)(n + 1) * G4 + r];

        ull a0 = 0ull, a1 = 0ull, a2 = 0ull, a3 = 0ull;
#pragma unroll
        for (int i = 0; i < 22; i++) {
            ulonglong2 hv = hb2[i];
            if (i & 1) { FMA2(a2, w[2 * i], hv.x); FMA2(a3, w[2 * i + 1], hv.y); }
            else       { FMA2(a0, w[2 * i], hv.x); FMA2(a1, w[2 * i + 1], hv.y); }
        }
#pragma unroll
        for (int i = 0; i < 10; i++) {
            ulonglong2 wv = sW2[i * 512 + t];
            ulonglong2 hv = hb2[22 + i];
            if (i & 1) { FMA2(a2, wv.x, hv.x); FMA2(a3, wv.y, hv.y); }
            else       { FMA2(a0, wv.x, hv.x); FMA2(a1, wv.y, hv.y); }
        }
        ADD2(a0, a0, a2);
        ADD2(a1, a1, a3);
        ADD2(a0, a0, a1);
        float a_lo, a_hi;
        asm("mov.b64 {%0, %1}, %2;" : "=f"(a_lo), "=f"(a_hi) : "l"(a0));
        float s = a_lo + a_hi + xv;

        float gate = (g == 2) ? tanh_f(s) : sigm_f(s);

        float i_ = __shfl_sync(0xffffffffu, gate, lanebase + 0);
        float f_ = __shfl_sync(0xffffffffu, gate, lanebase + 1);
        float gg = __shfl_sync(0xffffffffu, gate, lanebase + 2);
        float o_ = __shfl_sync(0xffffffffu, gate, lanebase + 3);

        c = f_ * c + i_ * gg;
        float hn = o_ * tanh_f(c);

        if (g == 0) {
            sh[((n + 1) & 1) * HL + u] = hn;
            hall[(size_t)n * HL + u] = hn;
        }
        xv = xnext;
        __syncthreads();

        if (LAYER == 0 && (n & (CHUNK - 1)) == (CHUNK - 1) && t == 0) {
            __threadfence();
            *((volatile int*)&g_prog1) = n + 1;   // release after block-wide barrier
        }
    }
}

__device__ __forceinline__ void gemm_body(int b, const float* __restrict__ h1all,
                                          const float* __restrict__ Wt,
                                          const float* __restrict__ ba,
                                          const float* __restrict__ bb,
                                          float* __restrict__ X2) {
    extern __shared__ ull dyn[];
    float (*As)[128] = (float (*)[128])dyn;    // 16x128 floats (8KB)
    const int t = threadIdx.x;                 // 512
    const float binit = ba[t] + bb[t];

    for (int ch = b; ch < NCHUNK; ch += NGB) {
        if (t == 0) {
            while (*((volatile int*)&g_prog1) < (ch + 1) * CHUNK) {}
            __threadfence();
        }
        __syncthreads();

        for (int sub = 0; sub < CHUNK / 16; sub++) {
            size_t row0 = (size_t)ch * CHUNK + sub * 16;
            for (int idx = t; idx < 16 * 128; idx += 512)
                As[idx >> 7][idx & 127] = __ldcg(&h1all[row0 * 128 + idx]);
            __syncthreads();

            float acc[16];
#pragma unroll
            for (int r = 0; r < 16; r++) acc[r] = binit;
#pragma unroll 4
            for (int k4 = 0; k4 < 32; k4++) {
                int k = k4 * 4;
                float w0 = Wt[(size_t)(k + 0) * G4 + t];
                float w1 = Wt[(size_t)(k + 1) * G4 + t];
                float w2 = Wt[(size_t)(k + 2) * G4 + t];
                float w3 = Wt[(size_t)(k + 3) * G4 + t];
#pragma unroll
                for (int r = 0; r < 16; r++) {
                    float4 a = ((const float4*)As[r])[k4];
                    acc[r] += a.x * w0 + a.y * w1 + a.z * w2 + a.w * w3;
                }
            }
#pragma unroll
            for (int r = 0; r < 16; r++)
                X2[(row0 + r) * G4 + t] = acc[r];
            __syncthreads();
        }
        if (t == 0) {
            __threadfence();
            ((volatile int*)g_x2ready)[ch] = 1;
        }
    }
}

__global__ __launch_bounds__(512, 1) void k_fused(
    const float* __restrict__ X1, const float* __restrict__ Whh1,
    const float* __restrict__ Whh2, const float* __restrict__ Wih2T,
    const float* __restrict__ bih2, const float* __restrict__ bhh2,
    float* __restrict__ h1all, float* __restrict__ X2, float* __restrict__ h2all) {
    const int role = blockIdx.x;
    if (role == 0) {
        scan_body<0>(X1, Whh1, h1all);
    } else if (role <= NGB) {
        gemm_body(role - 1, h1all, Wih2T, bih2, bhh2, X2);
    } else {
        scan_body<1>(X2, Whh2, h2all);
    }
}

// ---------------- final FC: out[n][c] = h2all[n] . Wfc[c] + bfc[c] ----------------
__global__ void k_fc(const float* __restrict__ h2all, const float* __restrict__ Wfc,
                     const float* __restrict__ bfc, float* __restrict__ out) {
    const int n = blockIdx.x;
    const int lane = threadIdx.x;
    float4 hv = ((const float4*)(h2all + (size_t)n * HL))[lane];
#pragma unroll
    for (int c = 0; c < CC; c++) {
        float4 w = ((const float4*)(Wfc + (size_t)c * HL))[lane];
        float p = hv.x * w.x + hv.y * w.y + hv.z * w.z + hv.w * w.w;
#pragma unroll
        for (int s = 16; s; s >>= 1) p += __shfl_xor_sync(0xffffffffu, p, s);
        if (lane == 0) out[n * CC + c] = p + bfc[c];
    }
}

// ---------------- launch ----------------
extern "C" void kernel_launch(void* const* d_in, const int* in_sizes, int n_in,
                              void* d_out, int out_size) {
    const float* x    = (const float*)d_in[0];
    const int*   ei   = (const int*)  d_in[1];
    const float* ew   = (const float*)d_in[2];
    const float* W1   = (const float*)d_in[3];
    const float* b1   = (const float*)d_in[4];
    const float* W2   = (const float*)d_in[5];
    const float* b2   = (const float*)d_in[6];
    const float* W3   = (const float*)d_in[7];
    const float* b3   = (const float*)d_in[8];
    const float* Wih1 = (const float*)d_in[9];
    const float* Whh1 = (const float*)d_in[10];
    const float* bih1 = (const float*)d_in[11];
    const float* bhh1 = (const float*)d_in[12];
    const float* Wih2 = (const float*)d_in[13];
    const float* Whh2 = (const float*)d_in[14];
    const float* bih2 = (const float*)d_in[15];
    const float* bhh2 = (const float*)d_in[16];
    const float* Wfc  = (const float*)d_in[17];
    const float* bfc  = (const float*)d_in[18];
    float* out = (float*)d_out;

    float *d_hw, *d_h, *d_X1, *d_X2, *d_h1all, *d_h2all, *d_Wih1T, *d_Wih2T;
    cudaGetSymbolAddress((void**)&d_hw,    g_hw);
    cudaGetSymbolAddress((void**)&d_h,     g_h);
    cudaGetSymbolAddress((void**)&d_X1,    g_X1);
    cudaGetSymbolAddress((void**)&d_X2,    g_X2);
    cudaGetSymbolAddress((void**)&d_h1all, g_h1all);
    cudaGetSymbolAddress((void**)&d_h2all, g_h2all);
    cudaGetSymbolAddress((void**)&d_Wih1T, g_Wih1T);
    cudaGetSymbolAddress((void**)&d_Wih2T, g_Wih2T);

    static int smem_set = 0;
    const int FUSED_SMEM = 1024 + 10 * 512 * 16;   // sh[2][128] + sW2 = 82944 B
    if (!smem_set) {
        cudaFuncSetAttribute(k_fused, cudaFuncAttributeMaxDynamicSharedMemorySize, FUSED_SMEM);
        smem_set = 1;
    }

    // graph preprocessing (CSR by destination) + degree norm + flag reset
    k_init<<<NN / 256, 256>>>();
    k_edge<<<EE / 256, 256>>>(ei, ew);
    k_dinv<<<NN / 256, 256>>>();
    k_scan<<<1, 1024>>>();
    k_fill<<<EE / 256, 256>>>(ei, ew);

    // transpose Wih weights to [K][OC]
    int trB = (HL * G4 + 255) / 256;
    k_tr<<<trB, 256>>>(Wih1, d_Wih1T, G4, HL);
    k_tr<<<trB, 256>>>(Wih2, d_Wih2T, G4, HL);

    // GCN on t=11 slice only (only slice that affects the output)
    const float* x11 = x + (size_t)11 * NN * FIN;
    k_gemm_kn<64, 128, 16, false><<<NN / 16, 128>>>(x11, W1, nullptr, nullptr, d_hw);
    k_gather<<<NN, 128>>>(d_hw, b1, d_h);
    k_gemm_kn<128, 128, 16, false><<<NN / 16, 128>>>(d_h, W2, nullptr, nullptr, d_hw);
    k_gather<<<NN, 128>>>(d_hw, b2, d_h);
    k_gemm_kn<128, 128, 16, false><<<NN / 16, 128>>>(d_h, W3, nullptr, nullptr, d_hw);
    k_gather<<<NN, 128>>>(d_hw, b3, d_h);

    // X1 = h @ Wih1^T + (bih1 + bhh1)
    k_gemm_kn<128, 512, 16, true><<<NN / 16, 512>>>(d_h, d_Wih1T, bih1, bhh1, d_X1);

    // fused pipelined: layer1 scan || streaming X2 GEMM || layer2 scan
    k_fused<<<NGB + 2, 512, FUSED_SMEM>>>(d_X1, Whh1, Whh2, d_Wih2T, bih2, bhh2,
                                          d_h1all, d_X2, d_h2all);

    // final FC
    k_fc<<<NN, 32>>>(d_h2all, Wfc, bfc, out);
}